// round 4
// baseline (speedup 1.0000x reference)
#include <cuda_runtime.h>

#define NN 256
#define BB 2
#define NNODE (BB*NN)

#define RSQRT3 0.5773502691896258f
#define INV_FAN 0.1767766952966369f   // 1/sqrt(32)

// scratch: G[node][f*4+c], f in [0,33) where f==32 is the bias (constant-1) feature
__device__ float g_G[NNODE][33*4];

#define PACK_F32X2(out, lo, hi) \
    asm("mov.b64 %0, {%1, %2};" : "=l"(out) : "f"(lo), "f"(hi))
#define UNPACK_F32X2(lo, hi, in) \
    asm("mov.b64 {%0, %1}, %2;" : "=f"(lo), "=f"(hi) : "l"(in))
#define FMA_F32X2(d, a, b, c) \
    asm("fma.rn.f32x2 %0, %1, %2, %3;" : "=l"(d) : "l"(a), "l"(b), "l"(c))
#define ADD_F32X2(d, a, b) \
    asm("add.rn.f32x2 %0, %1, %2;" : "=l"(d) : "l"(a), "l"(b))

#define CP_ASYNC16(dst_u32, src_ptr) \
    asm volatile("cp.async.ca.shared.global [%0], [%1], 16;" :: "r"(dst_u32), "l"(src_ptr))
#define CP_COMMIT() asm volatile("cp.async.commit_group;" ::: "memory")
#define CP_WAIT2()  asm volatile("cp.async.wait_group 2;" ::: "memory")
#define CP_WAIT1()  asm volatile("cp.async.wait_group 1;" ::: "memory")
#define CP_WAIT0()  asm volatile("cp.async.wait_group 0;" ::: "memory")

// ---------------------------------------------------------------------------
// Kernel A: per-(b,n) edge reduction, 3-buffer cp.async pipeline (64-row chunks)
// h[m,f] = relu(edge_attr[m,:] @ fc_w1[:,f] + fc_b1[f])
// G[f,c] = sum_m h[m,f] * sh'[m,c]   where sh' = edge_sh * mask * (m != n)
// G[32,c] = sum_m sh'[m,c]           (bias feature)
// ---------------------------------------------------------------------------
__global__ __launch_bounds__(256) void edge_kernel(
    const float* __restrict__ edge_attr,
    const float* __restrict__ edge_sh,
    const float* __restrict__ mask,
    const float* __restrict__ fc_w1,
    const float* __restrict__ fc_b1)
{
    __shared__ __align__(16) float ea[3][64 * 32];   // 3 x 8 KB chunks
    __shared__ __align__(16) float sh[NN * 4];       // premultiplied
    __shared__ float w1s[32 * 32];
    __shared__ float b1s[32];
    __shared__ float Gp[8][132];

    const int node = blockIdx.x;
    const int b = node >> 8;
    const int n = node & 255;
    const int t = threadIdx.x;

    const float* ea_g = edge_attr + (size_t)node * NN * 32;
    const float4* sh_g = (const float4*)(edge_sh + (size_t)node * NN * 4);
    float4* sh4 = (float4*)sh;

    const unsigned ea_u = (unsigned)__cvta_generic_to_shared(&ea[0][0]);

    // issue chunks 0 and 1
    #pragma unroll
    for (int ch = 0; ch < 2; ch++) {
        unsigned dst = ea_u + (unsigned)ch * 8192u + (unsigned)t * 16u;
        const float* src = ea_g + ch * 2048 + t * 4;
        CP_ASYNC16(dst, src);
        CP_ASYNC16(dst + 4096u, src + 1024);
        CP_COMMIT();
    }

    // prologue
    for (int i = t; i < 32 * 32; i += 256) w1s[i] = fc_w1[i];
    if (t < 32) b1s[t] = fc_b1[t];
    {
        float mf = mask[b * NN + t] * (t != n ? 1.0f : 0.0f);
        float4 s = sh_g[t];
        s.x *= mf; s.y *= mf; s.z *= mf; s.w *= mf;
        sh4[t] = s;
    }
    __syncthreads();

    const int f  = t & 31;
    const int mg = t >> 5;

    unsigned long long w1p[16];
    #pragma unroll
    for (int j = 0; j < 16; j++)
        PACK_F32X2(w1p[j], w1s[(2*j) * 32 + f], w1s[(2*j+1) * 32 + f]);
    const float bias1 = b1s[f];

    unsigned long long acc01 = 0ULL, acc23 = 0ULL;
    const ulonglong2* sh2 = (const ulonglong2*)sh;

    #pragma unroll
    for (int c = 0; c < 4; c++) {
        if (c >= 1) __syncthreads();   // buffer (c+2)%3 free
        if (c + 2 < 4) {
            int nc = c + 2;
            unsigned dst = ea_u + (unsigned)(nc % 3) * 8192u + (unsigned)t * 16u;
            const float* src = ea_g + nc * 2048 + t * 4;
            CP_ASYNC16(dst, src);
            CP_ASYNC16(dst + 4096u, src + 1024);
            CP_COMMIT();
        }
        if (c < 2) { CP_WAIT2(); } else if (c == 2) { CP_WAIT1(); } else { CP_WAIT0(); }
        __syncthreads();

        const float* buf = ea[c % 3];
        #pragma unroll
        for (int r = mg; r < 64; r += 16) {
            const ulonglong2* rA = (const ulonglong2*)(buf + r * 32);
            const ulonglong2* rB = (const ulonglong2*)(buf + (r + 8) * 32);
            unsigned long long cA0 = 0ULL, cA1 = 0ULL, cA2 = 0ULL, cA3 = 0ULL;
            unsigned long long cB0 = 0ULL, cB1 = 0ULL, cB2 = 0ULL, cB3 = 0ULL;
            #pragma unroll
            for (int k = 0; k < 4; k++) {
                ulonglong2 ua  = rA[2*k];
                ulonglong2 ua2 = rA[2*k + 1];
                ulonglong2 ub  = rB[2*k];
                ulonglong2 ub2 = rB[2*k + 1];
                FMA_F32X2(cA0, ua.x,  w1p[4*k+0], cA0);
                FMA_F32X2(cA1, ua.y,  w1p[4*k+1], cA1);
                FMA_F32X2(cA2, ua2.x, w1p[4*k+2], cA2);
                FMA_F32X2(cA3, ua2.y, w1p[4*k+3], cA3);
                FMA_F32X2(cB0, ub.x,  w1p[4*k+0], cB0);
                FMA_F32X2(cB1, ub.y,  w1p[4*k+1], cB1);
                FMA_F32X2(cB2, ub2.x, w1p[4*k+2], cB2);
                FMA_F32X2(cB3, ub2.y, w1p[4*k+3], cB3);
            }
            ADD_F32X2(cA0, cA0, cA1);
            ADD_F32X2(cA2, cA2, cA3);
            ADD_F32X2(cA0, cA0, cA2);
            ADD_F32X2(cB0, cB0, cB1);
            ADD_F32X2(cB2, cB2, cB3);
            ADD_F32X2(cB0, cB0, cB2);
            float a_lo, a_hi, b_lo, b_hi;
            UNPACK_F32X2(a_lo, a_hi, cA0);
            UNPACK_F32X2(b_lo, b_hi, cB0);
            float h0 = fmaxf(a_lo + a_hi + bias1, 0.0f);
            float h1 = fmaxf(b_lo + b_hi + bias1, 0.0f);
            unsigned long long h02, h12;
            PACK_F32X2(h02, h0, h0);
            PACK_F32X2(h12, h1, h1);
            ulonglong2 sa = sh2[c * 64 + r];
            ulonglong2 sb = sh2[c * 64 + r + 8];
            FMA_F32X2(acc01, h02, sa.x, acc01);
            FMA_F32X2(acc23, h02, sa.y, acc23);
            FMA_F32X2(acc01, h12, sb.x, acc01);
            FMA_F32X2(acc23, h12, sb.y, acc23);
        }
    }

    float o0, o1, o2, o3;
    UNPACK_F32X2(o0, o1, acc01);
    UNPACK_F32X2(o2, o3, acc23);
    Gp[mg][f*4+0] = o0;
    Gp[mg][f*4+1] = o1;
    Gp[mg][f*4+2] = o2;
    Gp[mg][f*4+3] = o3;

    // bias feature: G[32][c] = sum_m sh'[m][c]
    if (t < 32) {
        int c = t & 3, mq = t >> 2;
        float s = 0.f;
        #pragma unroll 8
        for (int m = mq; m < NN; m += 8) s += sh[m * 4 + c];
        Gp[mq][128 + c] = s;
    }
    __syncthreads();

    if (t < 132) {
        float s = 0.f;
        #pragma unroll
        for (int g = 0; g < 8; g++) s += Gp[g][t];
        g_G[node][t] = s;
    }
}

// ---------------------------------------------------------------------------
// Kernel B: per-node epilogue, 4 nodes/block, 128 blocks, 512 threads.
// Whole W2' (33x1024 incl. bias row) staged in smem via one cp.async group.
// Per-(f,i,node) coefficients precomputed to smem; main loop is pure
// LDS + FMA2 with zero syncthreads. Partial reduction reuses the W2 region.
// ---------------------------------------------------------------------------

// dynamic smem layout (floats)
#define OFF_STAGE   0                          // 33792 = W2' (then partials 256x132)
#define OFF_C       33792                      // 528*4*8 = 16896
#define OFF_GS      (OFF_C + 16896)            // 4*132
#define OFF_SIN     (OFF_GS + 528)             // 4*16
#define OFF_VIN     (OFF_SIN + 64)             // 4*48
#define OFF_WLS     (OFF_VIN + 192)
#define OFF_WLV     (OFF_WLS + 256)
#define OFF_WOS     (OFF_WLV + 256)
#define OFF_WOV     (OFF_WOS + 256)
#define OFF_OUTS    (OFF_WOV + 256)            // 4*16
#define OFF_OUTV    (OFF_OUTS + 64)            // 4*48
#define OFF_RED     (OFF_OUTV + 192)           // 8
#define OFF_DSUM    (OFF_RED + 8)              // 1
#define SMEM_FLOATS (OFF_DSUM + 1)
#define SMEM_BYTES  (SMEM_FLOATS * 4)

__device__ __forceinline__ void pair_compute(
    const float* __restrict__ stage, const float* __restrict__ C,
    int p, int oq,
    unsigned long long accS[4][2], unsigned long long accV[4][6])
{
    int f = p >> 4, i = p & 15;
    const ulonglong2* W = (const ulonglong2*)(stage + f * 1024 + i * 16 + oq * 4);
    ulonglong2 wss = W[0];
    ulonglong2 wvv = W[64];    // +256 floats
    ulonglong2 wsv = W[128];   // +512 floats
    ulonglong2 wvs = W[192];   // +768 floats
    #pragma unroll
    for (int nl = 0; nl < 4; nl++) {
        const ulonglong2* Cp = (const ulonglong2*)(C + ((p << 2) + nl) * 8);
        ulonglong2 cA = Cp[0], cB = Cp[1];
        float a, bc, c0, c1, c2, d0, d1, d2;
        UNPACK_F32X2(a, bc, cA.x);
        UNPACK_F32X2(c0, c1, cA.y);
        UNPACK_F32X2(c2, d0, cB.x);
        UNPACK_F32X2(d1, d2, cB.y);
        unsigned long long a2, bc2, c02, c12, c22, d02, d12, d22;
        PACK_F32X2(a2, a, a);   PACK_F32X2(bc2, bc, bc);
        PACK_F32X2(c02, c0, c0); PACK_F32X2(c12, c1, c1); PACK_F32X2(c22, c2, c2);
        PACK_F32X2(d02, d0, d0); PACK_F32X2(d12, d1, d1); PACK_F32X2(d22, d2, d2);
        FMA_F32X2(accS[nl][0], a2,  wss.x, accS[nl][0]);
        FMA_F32X2(accS[nl][1], a2,  wss.y, accS[nl][1]);
        FMA_F32X2(accS[nl][0], bc2, wvv.x, accS[nl][0]);
        FMA_F32X2(accS[nl][1], bc2, wvv.y, accS[nl][1]);
        FMA_F32X2(accV[nl][0], c02, wsv.x, accV[nl][0]);
        FMA_F32X2(accV[nl][1], c02, wsv.y, accV[nl][1]);
        FMA_F32X2(accV[nl][0], d02, wvs.x, accV[nl][0]);
        FMA_F32X2(accV[nl][1], d02, wvs.y, accV[nl][1]);
        FMA_F32X2(accV[nl][2], c12, wsv.x, accV[nl][2]);
        FMA_F32X2(accV[nl][3], c12, wsv.y, accV[nl][3]);
        FMA_F32X2(accV[nl][2], d12, wvs.x, accV[nl][2]);
        FMA_F32X2(accV[nl][3], d12, wvs.y, accV[nl][3]);
        FMA_F32X2(accV[nl][4], c22, wsv.x, accV[nl][4]);
        FMA_F32X2(accV[nl][5], c22, wsv.y, accV[nl][5]);
        FMA_F32X2(accV[nl][4], d22, wvs.x, accV[nl][4]);
        FMA_F32X2(accV[nl][5], d22, wvs.y, accV[nl][5]);
    }
}

__global__ __launch_bounds__(512) void node_kernel(
    const float* __restrict__ node_attr,
    const float* __restrict__ mask,
    const float* __restrict__ w_lin_in_s,
    const float* __restrict__ w_lin_in_v,
    const float* __restrict__ fc_w2,
    const float* __restrict__ fc_b2,
    const float* __restrict__ w_lin_out_s,
    const float* __restrict__ w_lin_out_v,
    float* __restrict__ out)
{
    extern __shared__ __align__(16) float sm[];
    float* stage = sm + OFF_STAGE;
    float* C     = sm + OFF_C;
    float* Gs    = sm + OFF_GS;
    float* sinS  = sm + OFF_SIN;
    float* vinS  = sm + OFF_VIN;
    float* wls   = sm + OFF_WLS;
    float* wlv   = sm + OFF_WLV;
    float* wos   = sm + OFF_WOS;
    float* wov   = sm + OFF_WOV;
    float* outsS = sm + OFF_OUTS;
    float* outvS = sm + OFF_OUTV;
    float* red   = sm + OFF_RED;

    const int t = threadIdx.x;
    const int node0 = blockIdx.x * 4;
    const int b = node0 >> 8;

    const unsigned stage_u32 = (unsigned)__cvta_generic_to_shared(stage);

    // --- one cp.async group: all of W2' (fc_w2 32x1024, fc_b2 as row 32) ---
    for (int i = t; i < 8448; i += 512) {
        const float* src = (i < 8192) ? (fc_w2 + i * 4) : (fc_b2 + (i - 8192) * 4);
        CP_ASYNC16(stage_u32 + (unsigned)i * 16u, src);
    }
    CP_COMMIT();

    // --- prologue: weights, G, mask reduce ---
    if (t < 256) {
        wls[t] = w_lin_in_s[t];
        wlv[t] = w_lin_in_v[t];
        wos[t] = w_lin_out_s[t];
        wov[t] = w_lin_out_v[t];
    }
    if (t < 132) {
        #pragma unroll
        for (int nl = 0; nl < 4; nl++) Gs[nl*132 + t] = g_G[node0 + nl][t];
    }
    if (t < 256) {
        float mv = mask[b * NN + t];
        #pragma unroll
        for (int o = 16; o; o >>= 1) mv += __shfl_xor_sync(0xFFFFFFFFu, mv, o);
        if ((t & 31) == 0) red[t >> 5] = mv;
    }
    __syncthreads();
    if (t == 0) {
        float s = 0.f;
        #pragma unroll
        for (int i = 0; i < 8; i++) s += red[i];
        sm[OFF_DSUM] = s - 1.0f;
    }

    // --- s_in / v_in ---
    if (t < 256) {
        int nl = t >> 6, u = t & 63;
        const float* na = node_attr + (size_t)(node0 + nl) * 64;
        if (u < 16) {
            float s = 0.f;
            #pragma unroll
            for (int i = 0; i < 16; i++) s += na[i] * wls[i * 16 + u];
            sinS[nl*16 + u] = s * 0.25f;
        } else {
            int idx = u - 16;
            int o = idx / 3, x = idx % 3;
            float s = 0.f;
            #pragma unroll
            for (int i = 0; i < 16; i++) s += na[16 + i * 3 + x] * wlv[i * 16 + o];
            vinS[nl*48 + o * 3 + x] = s * 0.25f;
        }
    }
    __syncthreads();

    // --- coefficient precompute: C[p][nl][8] = {a, bc, c0,c1,c2, d0,d1,d2} ---
    #pragma unroll
    for (int idx = t; idx < 2112; idx += 512) {
        int p = idx >> 2, nl = idx & 3;
        int fr = p >> 4, i = p & 15;
        const float* Gn = Gs + nl * 132 + fr * 4;
        float g0 = Gn[0], g1 = Gn[1], g2 = Gn[2], g3 = Gn[3];
        float si = sinS[nl*16 + i];
        float x0 = vinS[nl*48 + i*3 + 0];
        float x1 = vinS[nl*48 + i*3 + 1];
        float x2 = vinS[nl*48 + i*3 + 2];
        float* Cw = C + idx * 8;
        Cw[0] = g0 * si;
        Cw[1] = (g1 * x0 + g2 * x1 + g3 * x2) * RSQRT3;
        Cw[2] = g1 * si;
        Cw[3] = g2 * si;
        Cw[4] = g3 * si;
        Cw[5] = g0 * x0;
        Cw[6] = g0 * x1;
        Cw[7] = g0 * x2;
    }
    CP_WAIT0();
    __syncthreads();

    // --- main contraction: zero syncs ---
    const int oq = t & 3;
    const int g  = t >> 2;   // [0,128)

    unsigned long long accS[4][2];
    unsigned long long accV[4][6];
    #pragma unroll
    for (int nl = 0; nl < 4; nl++) {
        accS[nl][0] = accS[nl][1] = 0ULL;
        #pragma unroll
        for (int q = 0; q < 6; q++) accV[nl][q] = 0ULL;
    }

    #pragma unroll
    for (int pp = 0; pp < 4; pp++)
        pair_compute(stage, C, g + pp * 128, oq, accS, accV);
    if (g < 16)
        pair_compute(stage, C, 512 + g, oq, accS, accV);

    __syncthreads();   // all reads of W2 region done

    // --- stage partials into (dead) W2 region: [row 0..255][g 0..127], pitch 132 ---
    #pragma unroll
    for (int nl = 0; nl < 4; nl++) {
        #pragma unroll
        for (int h = 0; h < 2; h++) {
            float v0, v1;
            UNPACK_F32X2(v0, v1, accS[nl][h]);
            stage[(nl*16 + oq*4 + h*2 + 0) * 132 + g] = v0;
            stage[(nl*16 + oq*4 + h*2 + 1) * 132 + g] = v1;
        }
        #pragma unroll
        for (int x = 0; x < 3; x++)
            #pragma unroll
            for (int h = 0; h < 2; h++) {
                float v0, v1;
                UNPACK_F32X2(v0, v1, accV[nl][x*2 + h]);
                int o = oq*4 + h*2;
                stage[(64 + nl*48 + o*3 + x) * 132 + g] = v0;
                stage[(64 + nl*48 + (o+1)*3 + x) * 132 + g] = v1;
            }
    }
    __syncthreads();

    // --- reduce 128 partials per output, apply scale ---
    if (t < 256) {
        float scale = INV_FAN / sm[OFF_DSUM];
        const float4* row = (const float4*)(stage + t * 132);
        float s = 0.f;
        #pragma unroll
        for (int j = 0; j < 32; j++) {
            float4 v = row[j];
            s += (v.x + v.y) + (v.z + v.w);
        }
        if (t < 64) outsS[t] = s * scale;
        else        outvS[t - 64] = s * scale;
    }
    __syncthreads();

    // --- output linear (/4) + residual ---
    if (t < 256) {
        int nl = t >> 6, u = t & 63;
        const float* na = node_attr + (size_t)(node0 + nl) * 64;
        float r;
        if (u < 16) {
            float s = 0.f;
            #pragma unroll
            for (int o = 0; o < 16; o++) s += outsS[nl*16 + o] * wos[o * 16 + u];
            r = s * 0.25f + na[u];
        } else {
            int idx = u - 16;
            int o2 = idx / 3, x = idx % 3;
            float s = 0.f;
            #pragma unroll
            for (int o = 0; o < 16; o++) s += outvS[nl*48 + o * 3 + x] * wov[o * 16 + o2];
            r = s * 0.25f + na[u];
        }
        out[(size_t)(node0 + nl) * 64 + u] = r;
    }
}

extern "C" void kernel_launch(void* const* d_in, const int* in_sizes, int n_in,
                              void* d_out, int out_size) {
    const float* node_attr    = (const float*)d_in[0];
    const float* edge_attr    = (const float*)d_in[1];
    const float* edge_sh      = (const float*)d_in[2];
    const float* mask         = (const float*)d_in[3];
    const float* w_lin_in_s   = (const float*)d_in[4];
    const float* w_lin_in_v   = (const float*)d_in[5];
    const float* fc_w1        = (const float*)d_in[6];
    const float* fc_b1        = (const float*)d_in[7];
    const float* fc_w2        = (const float*)d_in[8];
    const float* fc_b2        = (const float*)d_in[9];
    const float* w_lin_out_s  = (const float*)d_in[10];
    const float* w_lin_out_v  = (const float*)d_in[11];
    float* out = (float*)d_out;

    cudaFuncSetAttribute(node_kernel,
                         cudaFuncAttributeMaxDynamicSharedMemorySize, SMEM_BYTES);

    edge_kernel<<<NNODE, 256>>>(edge_attr, edge_sh, mask, fc_w1, fc_b1);
    node_kernel<<<NNODE / 4, 512, SMEM_BYTES>>>(node_attr, mask,
                                    w_lin_in_s, w_lin_in_v,
                                    fc_w2, fc_b2, w_lin_out_s, w_lin_out_v, out);
}

// round 5
// speedup vs baseline: 1.0728x; 1.0728x over previous
#include <cuda_runtime.h>

#define NN 256
#define BB 2
#define NNODE (BB*NN)

#define RSQRT3 0.5773502691896258f
#define INV_FAN 0.1767766952966369f   // 1/sqrt(32)

// partial G: per (node, half) -> [f*4+c], f in [0,33), f==32 = bias feature
__device__ float g_G2[2*NNODE][132];

#define PACK_F32X2(out, lo, hi) \
    asm("mov.b64 %0, {%1, %2};" : "=l"(out) : "f"(lo), "f"(hi))
#define UNPACK_F32X2(lo, hi, in) \
    asm("mov.b64 {%0, %1}, %2;" : "=f"(lo), "=f"(hi) : "l"(in))
#define FMA_F32X2(d, a, b, c) \
    asm("fma.rn.f32x2 %0, %1, %2, %3;" : "=l"(d) : "l"(a), "l"(b), "l"(c))
#define ADD_F32X2(d, a, b) \
    asm("add.rn.f32x2 %0, %1, %2;" : "=l"(d) : "l"(a), "l"(b))

#define CP_ASYNC16(dst_u32, src_ptr) \
    asm volatile("cp.async.ca.shared.global [%0], [%1], 16;" :: "r"(dst_u32), "l"(src_ptr))
#define CP_COMMIT() asm volatile("cp.async.commit_group;" ::: "memory")
#define CP_WAIT2()  asm volatile("cp.async.wait_group 2;" ::: "memory")
#define CP_WAIT1()  asm volatile("cp.async.wait_group 1;" ::: "memory")
#define CP_WAIT0()  asm volatile("cp.async.wait_group 0;" ::: "memory")

// ---------------------------------------------------------------------------
// Kernel A: edge reduction, one block per (node, half): 128 m-rows per block.
// h[m,f] = relu(edge_attr[m,:] @ fc_w1[:,f] + fc_b1[f])
// Gpart[f,c] = sum_{m in half} h[m,f] * sh'[m,c],  sh' = edge_sh*mask*(m!=n)
// Gpart[32,c] = sum sh'[m,c]
// ---------------------------------------------------------------------------
__global__ __launch_bounds__(256) void edge_kernel(
    const float* __restrict__ edge_attr,
    const float* __restrict__ edge_sh,
    const float* __restrict__ mask,
    const float* __restrict__ fc_w1,
    const float* __restrict__ fc_b1)
{
    __shared__ __align__(16) float ea[2][64 * 32];   // 2 x 8 KB
    __shared__ __align__(16) float sh[128 * 4];      // premultiplied
    __shared__ float w1s[32 * 32];
    __shared__ float b1s[32];
    __shared__ float Gp[8][132];

    const int blk  = blockIdx.x;
    const int node = blk >> 1;
    const int half = blk & 1;
    const int b = node >> 8;
    const int n = node & 255;
    const int m0 = half * 128;
    const int t = threadIdx.x;

    const float* ea_g = edge_attr + (size_t)node * NN * 32 + (size_t)m0 * 32;
    const unsigned ea_u = (unsigned)__cvta_generic_to_shared(&ea[0][0]);

    // issue both 64-row chunks immediately
    CP_ASYNC16(ea_u + (unsigned)t * 16u, ea_g + t * 4);
    CP_ASYNC16(ea_u + 4096u + (unsigned)t * 16u, ea_g + 1024 + t * 4);
    CP_COMMIT();
    CP_ASYNC16(ea_u + 8192u + (unsigned)t * 16u, ea_g + 2048 + t * 4);
    CP_ASYNC16(ea_u + 12288u + (unsigned)t * 16u, ea_g + 3072 + t * 4);
    CP_COMMIT();

    // prologue (overlaps the cp.async)
    for (int i = t; i < 1024; i += 256) w1s[i] = fc_w1[i];
    if (t < 32) b1s[t] = fc_b1[t];
    if (t < 128) {
        int m = m0 + t;
        float mf = mask[b * NN + m] * (m != n ? 1.0f : 0.0f);
        float4 s = ((const float4*)(edge_sh + (size_t)node * NN * 4))[m];
        s.x *= mf; s.y *= mf; s.z *= mf; s.w *= mf;
        ((float4*)sh)[t] = s;
    }
    __syncthreads();

    const int f  = t & 31;
    const int mg = t >> 5;

    unsigned long long w1p[16];
    #pragma unroll
    for (int j = 0; j < 16; j++)
        PACK_F32X2(w1p[j], w1s[(2*j) * 32 + f], w1s[(2*j+1) * 32 + f]);
    unsigned long long bias2;
    PACK_F32X2(bias2, b1s[f], 0.0f);

    unsigned long long acc01 = 0ULL, acc23 = 0ULL;
    const ulonglong2* sh2 = (const ulonglong2*)sh;

    #pragma unroll
    for (int ch = 0; ch < 2; ch++) {
        if (ch == 0) { CP_WAIT1(); } else { CP_WAIT0(); }
        __syncthreads();
        const float* buf = ea[ch];
        #pragma unroll
        for (int it = 0; it < 4; it++) {
            int r = mg + it * 16;
            const ulonglong2* rA = (const ulonglong2*)(buf + r * 32);
            const ulonglong2* rB = (const ulonglong2*)(buf + (r + 8) * 32);
            unsigned long long cA0 = bias2, cA1 = 0ULL, cA2 = 0ULL, cA3 = 0ULL;
            unsigned long long cB0 = bias2, cB1 = 0ULL, cB2 = 0ULL, cB3 = 0ULL;
            #pragma unroll
            for (int k = 0; k < 4; k++) {
                ulonglong2 ua  = rA[2*k];
                ulonglong2 ua2 = rA[2*k + 1];
                ulonglong2 ub  = rB[2*k];
                ulonglong2 ub2 = rB[2*k + 1];
                FMA_F32X2(cA0, ua.x,  w1p[4*k+0], cA0);
                FMA_F32X2(cA1, ua.y,  w1p[4*k+1], cA1);
                FMA_F32X2(cA2, ua2.x, w1p[4*k+2], cA2);
                FMA_F32X2(cA3, ua2.y, w1p[4*k+3], cA3);
                FMA_F32X2(cB0, ub.x,  w1p[4*k+0], cB0);
                FMA_F32X2(cB1, ub.y,  w1p[4*k+1], cB1);
                FMA_F32X2(cB2, ub2.x, w1p[4*k+2], cB2);
                FMA_F32X2(cB3, ub2.y, w1p[4*k+3], cB3);
            }
            ADD_F32X2(cA0, cA0, cA1);
            ADD_F32X2(cA2, cA2, cA3);
            ADD_F32X2(cA0, cA0, cA2);
            ADD_F32X2(cB0, cB0, cB1);
            ADD_F32X2(cB2, cB2, cB3);
            ADD_F32X2(cB0, cB0, cB2);
            float a_lo, a_hi, b_lo, b_hi;
            UNPACK_F32X2(a_lo, a_hi, cA0);
            UNPACK_F32X2(b_lo, b_hi, cB0);
            float h0 = fmaxf(a_lo + a_hi, 0.0f);
            float h1 = fmaxf(b_lo + b_hi, 0.0f);
            unsigned long long h02, h12;
            PACK_F32X2(h02, h0, h0);
            PACK_F32X2(h12, h1, h1);
            ulonglong2 sa = sh2[ch * 64 + r];
            ulonglong2 sb = sh2[ch * 64 + r + 8];
            FMA_F32X2(acc01, h02, sa.x, acc01);
            FMA_F32X2(acc23, h02, sa.y, acc23);
            FMA_F32X2(acc01, h12, sb.x, acc01);
            FMA_F32X2(acc23, h12, sb.y, acc23);
        }
    }

    float o0, o1, o2, o3;
    UNPACK_F32X2(o0, o1, acc01);
    UNPACK_F32X2(o2, o3, acc23);
    Gp[mg][f*4+0] = o0;
    Gp[mg][f*4+1] = o1;
    Gp[mg][f*4+2] = o2;
    Gp[mg][f*4+3] = o3;

    // bias feature
    if (t < 32) {
        int c = t & 3, mq = t >> 2;
        float s = 0.f;
        #pragma unroll 8
        for (int m = mq; m < 128; m += 8) s += sh[m * 4 + c];
        Gp[mq][128 + c] = s;
    }
    __syncthreads();

    if (t < 132) {
        float s = 0.f;
        #pragma unroll
        for (int g = 0; g < 8; g++) s += Gp[g][t];
        g_G2[blk][t] = s;
    }
}

// ---------------------------------------------------------------------------
// Kernel B: per-node epilogue, 2 nodes/block, 256 blocks, 256 threads.
// W2' (33x1024, bias as row 32) streamed in 9 chunks of 4 rows through a
// 4-buffer cp.async pipeline, ONE barrier per chunk.
// ---------------------------------------------------------------------------

// dynamic smem layout (floats)
#define OFF_STAGE   0                          // 4 x 4096
#define OFF_PART    16384                      // 128 x 68
#define OFF_GS      (OFF_PART + 128*68)        // 2 x 132
#define OFF_SIN     (OFF_GS + 264)             // 2 x 16
#define OFF_VIN     (OFF_SIN + 32)             // 2 x 48
#define OFF_WLS     (OFF_VIN + 96)
#define OFF_WLV     (OFF_WLS + 256)
#define OFF_WOS     (OFF_WLV + 256)
#define OFF_WOV     (OFF_WOS + 256)
#define OFF_OUTS    (OFF_WOV + 256)            // 2 x 16
#define OFF_OUTV    (OFF_OUTS + 32)            // 2 x 48
#define OFF_RED     (OFF_OUTV + 96)            // 8
#define OFF_DSUM    (OFF_RED + 8)              // 1
#define SMEM_FLOATS (OFF_DSUM + 1)
#define SMEM_BYTES  (SMEM_FLOATS * 4)

__device__ __forceinline__ void chunk_compute(
    const float4* __restrict__ S, int nrows,
    const float* __restrict__ Gs, int fbase,
    const float* si, const float* x0a, const float* x1a, const float* x2a,
    float accS[2][4], float accV[2][12], int oq, int g)
{
    int f_local = g >> 4;
    int i = g & 15;
    if (f_local >= nrows) return;
    int base = f_local * 256 + i * 4 + oq;
    float4 wss = S[base];
    float4 wvv = S[base + 64];
    float4 wsv = S[base + 128];
    float4 wvs = S[base + 192];
    int fg = fbase + f_local;
    #pragma unroll
    for (int nl = 0; nl < 2; nl++) {
        const float* Gn = Gs + nl * 132 + fg * 4;
        float g0 = Gn[0], g1 = Gn[1], g2 = Gn[2], g3 = Gn[3];
        float s  = si[nl];
        float x0 = x0a[nl], x1 = x1a[nl], x2 = x2a[nl];
        float a  = g0 * s;
        float bc = (g1 * x0 + g2 * x1 + g3 * x2) * RSQRT3;
        accS[nl][0] += a * wss.x + bc * wvv.x;
        accS[nl][1] += a * wss.y + bc * wvv.y;
        accS[nl][2] += a * wss.z + bc * wvv.z;
        accS[nl][3] += a * wss.w + bc * wvv.w;
        float c0 = g1 * s, c1 = g2 * s, c2 = g3 * s;
        float d0 = g0 * x0, d1 = g0 * x1, d2 = g0 * x2;
        accV[nl][0]  += c0 * wsv.x + d0 * wvs.x;
        accV[nl][1]  += c0 * wsv.y + d0 * wvs.y;
        accV[nl][2]  += c0 * wsv.z + d0 * wvs.z;
        accV[nl][3]  += c0 * wsv.w + d0 * wvs.w;
        accV[nl][4]  += c1 * wsv.x + d1 * wvs.x;
        accV[nl][5]  += c1 * wsv.y + d1 * wvs.y;
        accV[nl][6]  += c1 * wsv.z + d1 * wvs.z;
        accV[nl][7]  += c1 * wsv.w + d1 * wvs.w;
        accV[nl][8]  += c2 * wsv.x + d2 * wvs.x;
        accV[nl][9]  += c2 * wsv.y + d2 * wvs.y;
        accV[nl][10] += c2 * wsv.z + d2 * wvs.z;
        accV[nl][11] += c2 * wsv.w + d2 * wvs.w;
    }
}

__device__ __forceinline__ void issue_chunk(
    unsigned stage_u32, int nc, int t,
    const float* __restrict__ fc_w2, const float* __restrict__ fc_b2)
{
    unsigned dst = stage_u32 + (unsigned)(nc & 3) * 16384u + (unsigned)t * 16u;
    if (nc < 8) {
        const float* src = fc_w2 + nc * 4096 + t * 4;
        #pragma unroll
        for (int r = 0; r < 4; r++)
            CP_ASYNC16(dst + r * 4096u, src + r * 1024);
    } else {
        CP_ASYNC16(dst, fc_b2 + t * 4);
    }
    CP_COMMIT();
}

__global__ __launch_bounds__(256, 2) void node_kernel(
    const float* __restrict__ node_attr,
    const float* __restrict__ mask,
    const float* __restrict__ w_lin_in_s,
    const float* __restrict__ w_lin_in_v,
    const float* __restrict__ fc_w2,
    const float* __restrict__ fc_b2,
    const float* __restrict__ w_lin_out_s,
    const float* __restrict__ w_lin_out_v,
    float* __restrict__ out)
{
    extern __shared__ __align__(16) float sm[];
    float* stage = sm + OFF_STAGE;
    float* part  = sm + OFF_PART;
    float* Gs    = sm + OFF_GS;
    float* sinS  = sm + OFF_SIN;
    float* vinS  = sm + OFF_VIN;
    float* wls   = sm + OFF_WLS;
    float* wlv   = sm + OFF_WLV;
    float* wos   = sm + OFF_WOS;
    float* wov   = sm + OFF_WOV;
    float* outsS = sm + OFF_OUTS;
    float* outvS = sm + OFF_OUTV;
    float* red   = sm + OFF_RED;

    const int t = threadIdx.x;
    const int node0 = blockIdx.x * 2;
    const int b = node0 >> 8;

    const unsigned stage_u32 = (unsigned)__cvta_generic_to_shared(stage);

    // prefetch chunks 0..2 (3 groups outstanding)
    issue_chunk(stage_u32, 0, t, fc_w2, fc_b2);
    issue_chunk(stage_u32, 1, t, fc_w2, fc_b2);
    issue_chunk(stage_u32, 2, t, fc_w2, fc_b2);

    // --- prologue ---
    wls[t] = w_lin_in_s[t];
    wlv[t] = w_lin_in_v[t];
    wos[t] = w_lin_out_s[t];
    wov[t] = w_lin_out_v[t];
    if (t < 132) {
        #pragma unroll
        for (int nl = 0; nl < 2; nl++)
            Gs[nl*132 + t] = g_G2[(node0 + nl)*2][t] + g_G2[(node0 + nl)*2 + 1][t];
    }
    {
        float mv = mask[b * NN + t];
        #pragma unroll
        for (int o = 16; o; o >>= 1) mv += __shfl_xor_sync(0xFFFFFFFFu, mv, o);
        if ((t & 31) == 0) red[t >> 5] = mv;
    }
    __syncthreads();
    if (t == 0) {
        float s = 0.f;
        #pragma unroll
        for (int i = 0; i < 8; i++) s += red[i];
        sm[OFF_DSUM] = s - 1.0f;
    }

    // --- s_in / v_in (128 active threads, 2 nodes) ---
    if (t < 128) {
        int nl = t >> 6, u = t & 63;
        const float* na = node_attr + (size_t)(node0 + nl) * 64;
        if (u < 16) {
            float s = 0.f;
            #pragma unroll
            for (int i = 0; i < 16; i++) s += na[i] * wls[i * 16 + u];
            sinS[nl*16 + u] = s * 0.25f;
        } else {
            int idx = u - 16;
            int o = idx / 3, x = idx % 3;
            float s = 0.f;
            #pragma unroll
            for (int i = 0; i < 16; i++) s += na[16 + i * 3 + x] * wlv[i * 16 + o];
            vinS[nl*48 + o * 3 + x] = s * 0.25f;
        }
    }
    __syncthreads();

    // --- streamed contraction: ONE barrier per chunk ---
    const int oq = t & 3;
    const int g  = t >> 2;   // [0,64)

    float si[2], x0a[2], x1a[2], x2a[2];
    {
        int i = g & 15;
        #pragma unroll
        for (int nl = 0; nl < 2; nl++) {
            si[nl]  = sinS[nl*16 + i];
            x0a[nl] = vinS[nl*48 + i*3 + 0];
            x1a[nl] = vinS[nl*48 + i*3 + 1];
            x2a[nl] = vinS[nl*48 + i*3 + 2];
        }
    }

    float accS[2][4];
    float accV[2][12];
    #pragma unroll
    for (int nl = 0; nl < 2; nl++) {
        #pragma unroll
        for (int q = 0; q < 4; q++) accS[nl][q] = 0.f;
        #pragma unroll
        for (int q = 0; q < 12; q++) accV[nl][q] = 0.f;
    }

    #pragma unroll
    for (int c = 0; c < 9; c++) {
        if (c < 7) { CP_WAIT2(); } else if (c == 7) { CP_WAIT1(); } else { CP_WAIT0(); }
        __syncthreads();
        // buffer (c+3)&3 was consumed at iteration c-1; safe to refill now
        if (c + 3 <= 8) issue_chunk(stage_u32, c + 3, t, fc_w2, fc_b2);
        const float4* S = (const float4*)(stage + (c & 3) * 4096);
        chunk_compute(S, (c < 8) ? 4 : 1, Gs, c * 4,
                      si, x0a, x1a, x2a, accS, accV, oq, g);
    }

    __syncthreads();

    // --- stage partials: rows 0..31 = S(nl,o), rows 32..127 = V(nl,o,x) ---
    #pragma unroll
    for (int nl = 0; nl < 2; nl++) {
        #pragma unroll
        for (int q = 0; q < 4; q++)
            part[(nl*16 + oq*4 + q) * 68 + g] = accS[nl][q];
        #pragma unroll
        for (int x = 0; x < 3; x++)
            #pragma unroll
            for (int q = 0; q < 4; q++)
                part[(32 + nl*48 + (oq*4 + q)*3 + x) * 68 + g] = accV[nl][x*4 + q];
    }
    __syncthreads();

    // --- reduce over 64 groups, apply scale ---
    if (t < 128) {
        float scale = INV_FAN / sm[OFF_DSUM];
        const float4* row = (const float4*)(part + t * 68);
        float s = 0.f;
        #pragma unroll
        for (int j = 0; j < 16; j++) {
            float4 v = row[j];
            s += (v.x + v.y) + (v.z + v.w);
        }
        if (t < 32) outsS[t] = s * scale;
        else        outvS[t - 32] = s * scale;
    }
    __syncthreads();

    // --- output linear (/4) + residual ---
    if (t < 128) {
        int nl = t >> 6, u = t & 63;
        const float* na = node_attr + (size_t)(node0 + nl) * 64;
        float r;
        if (u < 16) {
            float s = 0.f;
            #pragma unroll
            for (int o = 0; o < 16; o++) s += outsS[nl*16 + o] * wos[o * 16 + u];
            r = s * 0.25f + na[u];
        } else {
            int idx = u - 16;
            int o2 = idx / 3, x = idx % 3;
            float s = 0.f;
            #pragma unroll
            for (int o = 0; o < 16; o++) s += outvS[nl*48 + o * 3 + x] * wov[o * 16 + o2];
            r = s * 0.25f + na[u];
        }
        out[(size_t)(node0 + nl) * 64 + u] = r;
    }
}

extern "C" void kernel_launch(void* const* d_in, const int* in_sizes, int n_in,
                              void* d_out, int out_size) {
    const float* node_attr    = (const float*)d_in[0];
    const float* edge_attr    = (const float*)d_in[1];
    const float* edge_sh      = (const float*)d_in[2];
    const float* mask         = (const float*)d_in[3];
    const float* w_lin_in_s   = (const float*)d_in[4];
    const float* w_lin_in_v   = (const float*)d_in[5];
    const float* fc_w1        = (const float*)d_in[6];
    const float* fc_b1        = (const float*)d_in[7];
    const float* fc_w2        = (const float*)d_in[8];
    const float* fc_b2        = (const float*)d_in[9];
    const float* w_lin_out_s  = (const float*)d_in[10];
    const float* w_lin_out_v  = (const float*)d_in[11];
    float* out = (float*)d_out;

    cudaFuncSetAttribute(node_kernel,
                         cudaFuncAttributeMaxDynamicSharedMemorySize, SMEM_BYTES);

    edge_kernel<<<2 * NNODE, 256>>>(edge_attr, edge_sh, mask, fc_w1, fc_b1);
    node_kernel<<<NNODE / 2, 256, SMEM_BYTES>>>(node_attr, mask,
                                    w_lin_in_s, w_lin_in_v,
                                    fc_w2, fc_b2, w_lin_out_s, w_lin_out_v, out);
}

// round 6
// speedup vs baseline: 1.1667x; 1.0875x over previous
#include <cuda_runtime.h>

#define NN 256
#define BB 2
#define NNODE (BB*NN)

#define RSQRT3 0.5773502691896258f
#define INV_FAN 0.1767766952966369f   // 1/sqrt(32)

// partial G: per (node, half) -> [f*4+c], f in [0,33), f==32 = bias feature
__device__ float g_G2[2*NNODE][132];

#define PACK_F32X2(out, lo, hi) \
    asm("mov.b64 %0, {%1, %2};" : "=l"(out) : "f"(lo), "f"(hi))
#define UNPACK_F32X2(lo, hi, in) \
    asm("mov.b64 {%0, %1}, %2;" : "=f"(lo), "=f"(hi) : "l"(in))
#define FMA_F32X2(d, a, b, c) \
    asm("fma.rn.f32x2 %0, %1, %2, %3;" : "=l"(d) : "l"(a), "l"(b), "l"(c))
#define ADD_F32X2(d, a, b) \
    asm("add.rn.f32x2 %0, %1, %2;" : "=l"(d) : "l"(a), "l"(b))

#define CP_ASYNC16(dst_u32, src_ptr) \
    asm volatile("cp.async.ca.shared.global [%0], [%1], 16;" :: "r"(dst_u32), "l"(src_ptr))
#define CP_COMMIT() asm volatile("cp.async.commit_group;" ::: "memory")
#define CP_WAIT2()  asm volatile("cp.async.wait_group 2;" ::: "memory")
#define CP_WAIT1()  asm volatile("cp.async.wait_group 1;" ::: "memory")
#define CP_WAIT0()  asm volatile("cp.async.wait_group 0;" ::: "memory")

// ---------------------------------------------------------------------------
// Kernel A: edge reduction, one block per (node, half): 128 m-rows per block.
// ---------------------------------------------------------------------------
__global__ __launch_bounds__(256, 3) void edge_kernel(
    const float* __restrict__ edge_attr,
    const float* __restrict__ edge_sh,
    const float* __restrict__ mask,
    const float* __restrict__ fc_w1,
    const float* __restrict__ fc_b1)
{
    __shared__ __align__(16) float ea[2][64 * 32];   // 2 x 8 KB
    __shared__ __align__(16) float sh[128 * 4];      // premultiplied
    __shared__ float w1s[32 * 32];
    __shared__ float b1s[32];
    __shared__ float Gp[8][132];

    const int blk  = blockIdx.x;
    const int node = blk >> 1;
    const int half = blk & 1;
    const int b = node >> 8;
    const int n = node & 255;
    const int m0 = half * 128;
    const int t = threadIdx.x;

    const float* ea_g = edge_attr + (size_t)node * NN * 32 + (size_t)m0 * 32;
    const unsigned ea_u = (unsigned)__cvta_generic_to_shared(&ea[0][0]);

    // issue both 64-row chunks immediately
    CP_ASYNC16(ea_u + (unsigned)t * 16u, ea_g + t * 4);
    CP_ASYNC16(ea_u + 4096u + (unsigned)t * 16u, ea_g + 1024 + t * 4);
    CP_COMMIT();
    CP_ASYNC16(ea_u + 8192u + (unsigned)t * 16u, ea_g + 2048 + t * 4);
    CP_ASYNC16(ea_u + 12288u + (unsigned)t * 16u, ea_g + 3072 + t * 4);
    CP_COMMIT();

    // prologue (overlaps the cp.async)
    for (int i = t; i < 1024; i += 256) w1s[i] = fc_w1[i];
    if (t < 32) b1s[t] = fc_b1[t];
    if (t < 128) {
        int m = m0 + t;
        float mf = mask[b * NN + m] * (m != n ? 1.0f : 0.0f);
        float4 s = ((const float4*)(edge_sh + (size_t)node * NN * 4))[m];
        s.x *= mf; s.y *= mf; s.z *= mf; s.w *= mf;
        ((float4*)sh)[t] = s;
    }
    __syncthreads();

    const int f  = t & 31;
    const int mg = t >> 5;

    unsigned long long w1p[16];
    #pragma unroll
    for (int j = 0; j < 16; j++)
        PACK_F32X2(w1p[j], w1s[(2*j) * 32 + f], w1s[(2*j+1) * 32 + f]);
    unsigned long long bias2;
    PACK_F32X2(bias2, b1s[f], 0.0f);

    unsigned long long acc01 = 0ULL, acc23 = 0ULL;
    const ulonglong2* sh2 = (const ulonglong2*)sh;

    #pragma unroll
    for (int ch = 0; ch < 2; ch++) {
        if (ch == 0) { CP_WAIT1(); } else { CP_WAIT0(); }
        __syncthreads();
        const float* buf = ea[ch];
        #pragma unroll
        for (int it = 0; it < 8; it++) {
            int r = mg + it * 8;
            const ulonglong2* row = (const ulonglong2*)(buf + r * 32);
            ulonglong2 u0 = row[0];
            ulonglong2 u1 = row[1];
            ulonglong2 u2 = row[2];
            ulonglong2 u3 = row[3];
            unsigned long long c0 = bias2, c1 = 0ULL, c2 = 0ULL, c3 = 0ULL;
            FMA_F32X2(c0, u0.x, w1p[0], c0);
            FMA_F32X2(c1, u0.y, w1p[1], c1);
            FMA_F32X2(c2, u1.x, w1p[2], c2);
            FMA_F32X2(c3, u1.y, w1p[3], c3);
            FMA_F32X2(c0, u2.x, w1p[4], c0);
            FMA_F32X2(c1, u2.y, w1p[5], c1);
            FMA_F32X2(c2, u3.x, w1p[6], c2);
            FMA_F32X2(c3, u3.y, w1p[7], c3);
            u0 = row[4];
            u1 = row[5];
            u2 = row[6];
            u3 = row[7];
            FMA_F32X2(c0, u0.x, w1p[8],  c0);
            FMA_F32X2(c1, u0.y, w1p[9],  c1);
            FMA_F32X2(c2, u1.x, w1p[10], c2);
            FMA_F32X2(c3, u1.y, w1p[11], c3);
            FMA_F32X2(c0, u2.x, w1p[12], c0);
            FMA_F32X2(c1, u2.y, w1p[13], c1);
            FMA_F32X2(c2, u3.x, w1p[14], c2);
            FMA_F32X2(c3, u3.y, w1p[15], c3);
            ADD_F32X2(c0, c0, c1);
            ADD_F32X2(c2, c2, c3);
            ADD_F32X2(c0, c0, c2);
            float lo, hi;
            UNPACK_F32X2(lo, hi, c0);
            float h = fmaxf(lo + hi, 0.0f);
            unsigned long long h2;
            PACK_F32X2(h2, h, h);
            ulonglong2 s2 = sh2[ch * 64 + r];
            FMA_F32X2(acc01, h2, s2.x, acc01);
            FMA_F32X2(acc23, h2, s2.y, acc23);
        }
    }

    float o0, o1, o2, o3;
    UNPACK_F32X2(o0, o1, acc01);
    UNPACK_F32X2(o2, o3, acc23);
    Gp[mg][f*4+0] = o0;
    Gp[mg][f*4+1] = o1;
    Gp[mg][f*4+2] = o2;
    Gp[mg][f*4+3] = o3;

    // bias feature: G[32][c] = sum_m sh'[m][c]
    if (t < 32) {
        int c = t & 3, mq = t >> 2;
        float s = 0.f;
        #pragma unroll 8
        for (int m = mq; m < 128; m += 8) s += sh[m * 4 + c];
        Gp[mq][128 + c] = s;
    }
    __syncthreads();

    if (t < 132) {
        float s = 0.f;
        #pragma unroll
        for (int g = 0; g < 8; g++) s += Gp[g][t];
        g_G2[blk][t] = s;
    }
}

// ---------------------------------------------------------------------------
// Kernel B: per-node epilogue, 2 nodes/block, 256 blocks, 256 threads.
// W2' streamed in 9 chunks through 4 smem buffers (one barrier per chunk).
// o-dimension packed as f32x2. Partials overlay the stage region.
// ---------------------------------------------------------------------------

// dynamic smem layout (floats)
#define OFF_STAGE   0                          // 4 x 4096 (reused for partials)
#define OFF_GS      16384                      // 2 x 132
#define OFF_SIN     (OFF_GS + 264)             // 2 x 16
#define OFF_VIN     (OFF_SIN + 32)             // 2 x 48
#define OFF_WLS     (OFF_VIN + 96)
#define OFF_WLV     (OFF_WLS + 256)
#define OFF_WOS     (OFF_WLV + 256)
#define OFF_WOV     (OFF_WOS + 256)
#define OFF_OUTS    (OFF_WOV + 256)            // 2 x 16
#define OFF_OUTV    (OFF_OUTS + 32)            // 2 x 48
#define OFF_RED     (OFF_OUTV + 96)            // 8
#define OFF_DSUM    (OFF_RED + 8)              // 1
#define SMEM_FLOATS (OFF_DSUM + 1)
#define SMEM_BYTES  (SMEM_FLOATS * 4)

__device__ __forceinline__ void chunk_compute_p(
    const float* __restrict__ stage_buf, int nrows,
    const float* __restrict__ Gs, int fbase,
    const float* si, const float* x0a, const float* x1a, const float* x2a,
    unsigned long long accS[2][2], unsigned long long accV[2][6],
    int oq, int g)
{
    int f_local = g >> 4;
    int i = g & 15;
    if (f_local >= nrows) return;
    const ulonglong2* W = (const ulonglong2*)(stage_buf + f_local * 1024 + i * 16 + oq * 4);
    ulonglong2 wss = W[0];
    ulonglong2 wvv = W[64];
    ulonglong2 wsv = W[128];
    ulonglong2 wvs = W[192];
    #pragma unroll
    for (int nl = 0; nl < 2; nl++) {
        float4 gv = *(const float4*)(Gs + nl * 132 + (fbase + f_local) * 4);
        float s  = si[nl];
        float x0 = x0a[nl], x1 = x1a[nl], x2 = x2a[nl];
        float a  = gv.x * s;
        float bc = (gv.y * x0 + gv.z * x1 + gv.w * x2) * RSQRT3;
        float c0 = gv.y * s, c1 = gv.z * s, c2 = gv.w * s;
        float d0 = gv.x * x0, d1 = gv.x * x1, d2 = gv.x * x2;
        unsigned long long a2, bc2, c02, c12, c22, d02, d12, d22;
        PACK_F32X2(a2, a, a);     PACK_F32X2(bc2, bc, bc);
        PACK_F32X2(c02, c0, c0);  PACK_F32X2(c12, c1, c1);  PACK_F32X2(c22, c2, c2);
        PACK_F32X2(d02, d0, d0);  PACK_F32X2(d12, d1, d1);  PACK_F32X2(d22, d2, d2);
        FMA_F32X2(accS[nl][0], a2,  wss.x, accS[nl][0]);
        FMA_F32X2(accS[nl][1], a2,  wss.y, accS[nl][1]);
        FMA_F32X2(accS[nl][0], bc2, wvv.x, accS[nl][0]);
        FMA_F32X2(accS[nl][1], bc2, wvv.y, accS[nl][1]);
        FMA_F32X2(accV[nl][0], c02, wsv.x, accV[nl][0]);
        FMA_F32X2(accV[nl][1], c02, wsv.y, accV[nl][1]);
        FMA_F32X2(accV[nl][0], d02, wvs.x, accV[nl][0]);
        FMA_F32X2(accV[nl][1], d02, wvs.y, accV[nl][1]);
        FMA_F32X2(accV[nl][2], c12, wsv.x, accV[nl][2]);
        FMA_F32X2(accV[nl][3], c12, wsv.y, accV[nl][3]);
        FMA_F32X2(accV[nl][2], d12, wvs.x, accV[nl][2]);
        FMA_F32X2(accV[nl][3], d12, wvs.y, accV[nl][3]);
        FMA_F32X2(accV[nl][4], c22, wsv.x, accV[nl][4]);
        FMA_F32X2(accV[nl][5], c22, wsv.y, accV[nl][5]);
        FMA_F32X2(accV[nl][4], d22, wvs.x, accV[nl][4]);
        FMA_F32X2(accV[nl][5], d22, wvs.y, accV[nl][5]);
    }
}

__device__ __forceinline__ void issue_chunk(
    unsigned stage_u32, int nc, int t,
    const float* __restrict__ fc_w2, const float* __restrict__ fc_b2)
{
    unsigned dst = stage_u32 + (unsigned)(nc & 3) * 16384u + (unsigned)t * 16u;
    if (nc < 8) {
        const float* src = fc_w2 + nc * 4096 + t * 4;
        #pragma unroll
        for (int r = 0; r < 4; r++)
            CP_ASYNC16(dst + r * 4096u, src + r * 1024);
    } else {
        CP_ASYNC16(dst, fc_b2 + t * 4);
    }
    CP_COMMIT();
}

__global__ __launch_bounds__(256, 3) void node_kernel(
    const float* __restrict__ node_attr,
    const float* __restrict__ mask,
    const float* __restrict__ w_lin_in_s,
    const float* __restrict__ w_lin_in_v,
    const float* __restrict__ fc_w2,
    const float* __restrict__ fc_b2,
    const float* __restrict__ w_lin_out_s,
    const float* __restrict__ w_lin_out_v,
    float* __restrict__ out)
{
    extern __shared__ __align__(16) float sm[];
    float* stage = sm + OFF_STAGE;
    float* part  = sm + OFF_STAGE;    // overlays stage after consumption
    float* Gs    = sm + OFF_GS;
    float* sinS  = sm + OFF_SIN;
    float* vinS  = sm + OFF_VIN;
    float* wls   = sm + OFF_WLS;
    float* wlv   = sm + OFF_WLV;
    float* wos   = sm + OFF_WOS;
    float* wov   = sm + OFF_WOV;
    float* outsS = sm + OFF_OUTS;
    float* outvS = sm + OFF_OUTV;
    float* red   = sm + OFF_RED;

    const int t = threadIdx.x;
    const int node0 = blockIdx.x * 2;
    const int b = node0 >> 8;

    const unsigned stage_u32 = (unsigned)__cvta_generic_to_shared(stage);

    // prefetch chunks 0..2 (3 groups outstanding)
    issue_chunk(stage_u32, 0, t, fc_w2, fc_b2);
    issue_chunk(stage_u32, 1, t, fc_w2, fc_b2);
    issue_chunk(stage_u32, 2, t, fc_w2, fc_b2);

    // --- prologue ---
    wls[t] = w_lin_in_s[t];
    wlv[t] = w_lin_in_v[t];
    wos[t] = w_lin_out_s[t];
    wov[t] = w_lin_out_v[t];
    if (t < 132) {
        #pragma unroll
        for (int nl = 0; nl < 2; nl++)
            Gs[nl*132 + t] = g_G2[(node0 + nl)*2][t] + g_G2[(node0 + nl)*2 + 1][t];
    }
    {
        float mv = mask[b * NN + t];
        #pragma unroll
        for (int o = 16; o; o >>= 1) mv += __shfl_xor_sync(0xFFFFFFFFu, mv, o);
        if ((t & 31) == 0) red[t >> 5] = mv;
    }
    __syncthreads();
    if (t == 0) {
        float s = 0.f;
        #pragma unroll
        for (int i = 0; i < 8; i++) s += red[i];
        sm[OFF_DSUM] = s - 1.0f;
    }

    // --- s_in / v_in ---
    if (t < 128) {
        int nl = t >> 6, u = t & 63;
        const float* na = node_attr + (size_t)(node0 + nl) * 64;
        if (u < 16) {
            float s = 0.f;
            #pragma unroll
            for (int i = 0; i < 16; i++) s += na[i] * wls[i * 16 + u];
            sinS[nl*16 + u] = s * 0.25f;
        } else {
            int idx = u - 16;
            int o = idx / 3, x = idx % 3;
            float s = 0.f;
            #pragma unroll
            for (int i = 0; i < 16; i++) s += na[16 + i * 3 + x] * wlv[i * 16 + o];
            vinS[nl*48 + o * 3 + x] = s * 0.25f;
        }
    }
    __syncthreads();

    // --- streamed contraction ---
    const int oq = t & 3;
    const int g  = t >> 2;   // [0,64)

    float si[2], x0a[2], x1a[2], x2a[2];
    {
        int i = g & 15;
        #pragma unroll
        for (int nl = 0; nl < 2; nl++) {
            si[nl]  = sinS[nl*16 + i];
            x0a[nl] = vinS[nl*48 + i*3 + 0];
            x1a[nl] = vinS[nl*48 + i*3 + 1];
            x2a[nl] = vinS[nl*48 + i*3 + 2];
        }
    }

    unsigned long long accS[2][2];
    unsigned long long accV[2][6];
    #pragma unroll
    for (int nl = 0; nl < 2; nl++) {
        accS[nl][0] = accS[nl][1] = 0ULL;
        #pragma unroll
        for (int q = 0; q < 6; q++) accV[nl][q] = 0ULL;
    }

    #pragma unroll
    for (int c = 0; c < 9; c++) {
        if (c < 7) { CP_WAIT2(); } else if (c == 7) { CP_WAIT1(); } else { CP_WAIT0(); }
        __syncthreads();
        if (c + 3 <= 8) issue_chunk(stage_u32, c + 3, t, fc_w2, fc_b2);
        chunk_compute_p(stage + (c & 3) * 4096, (c < 8) ? 4 : 1, Gs, c * 4,
                        si, x0a, x1a, x2a, accS, accV, oq, g);
    }

    __syncthreads();   // all stage reads done; safe to overlay partials

    // --- stage partials: rows 0..31 = S(nl,o), rows 32..127 = V(nl,o,x) ---
    #pragma unroll
    for (int nl = 0; nl < 2; nl++) {
        #pragma unroll
        for (int h = 0; h < 2; h++) {
            float v0, v1;
            UNPACK_F32X2(v0, v1, accS[nl][h]);
            part[(nl*16 + oq*4 + h*2 + 0) * 68 + g] = v0;
            part[(nl*16 + oq*4 + h*2 + 1) * 68 + g] = v1;
        }
        #pragma unroll
        for (int x = 0; x < 3; x++)
            #pragma unroll
            for (int h = 0; h < 2; h++) {
                float v0, v1;
                UNPACK_F32X2(v0, v1, accV[nl][x*2 + h]);
                int o = oq*4 + h*2;
                part[(32 + nl*48 + o*3 + x) * 68 + g] = v0;
                part[(32 + nl*48 + (o+1)*3 + x) * 68 + g] = v1;
            }
    }
    __syncthreads();

    // --- reduce over 64 groups, apply scale ---
    if (t < 128) {
        float scale = INV_FAN / sm[OFF_DSUM];
        const float4* row = (const float4*)(part + t * 68);
        float s = 0.f;
        #pragma unroll
        for (int j = 0; j < 16; j++) {
            float4 v = row[j];
            s += (v.x + v.y) + (v.z + v.w);
        }
        if (t < 32) outsS[t] = s * scale;
        else        outvS[t - 32] = s * scale;
    }
    __syncthreads();

    // --- output linear (/4) + residual ---
    if (t < 128) {
        int nl = t >> 6, u = t & 63;
        const float* na = node_attr + (size_t)(node0 + nl) * 64;
        float r;
        if (u < 16) {
            float s = 0.f;
            #pragma unroll
            for (int o = 0; o < 16; o++) s += outsS[nl*16 + o] * wos[o * 16 + u];
            r = s * 0.25f + na[u];
        } else {
            int idx = u - 16;
            int o2 = idx / 3, x = idx % 3;
            float s = 0.f;
            #pragma unroll
            for (int o = 0; o < 16; o++) s += outvS[nl*48 + o * 3 + x] * wov[o * 16 + o2];
            r = s * 0.25f + na[u];
        }
        out[(size_t)(node0 + nl) * 64 + u] = r;
    }
}

extern "C" void kernel_launch(void* const* d_in, const int* in_sizes, int n_in,
                              void* d_out, int out_size) {
    const float* node_attr    = (const float*)d_in[0];
    const float* edge_attr    = (const float*)d_in[1];
    const float* edge_sh      = (const float*)d_in[2];
    const float* mask         = (const float*)d_in[3];
    const float* w_lin_in_s   = (const float*)d_in[4];
    const float* w_lin_in_v   = (const float*)d_in[5];
    const float* fc_w1        = (const float*)d_in[6];
    const float* fc_b1        = (const float*)d_in[7];
    const float* fc_w2        = (const float*)d_in[8];
    const float* fc_b2        = (const float*)d_in[9];
    const float* w_lin_out_s  = (const float*)d_in[10];
    const float* w_lin_out_v  = (const float*)d_in[11];
    float* out = (float*)d_out;

    cudaFuncSetAttribute(node_kernel,
                         cudaFuncAttributeMaxDynamicSharedMemorySize, SMEM_BYTES);

    edge_kernel<<<2 * NNODE, 256>>>(edge_attr, edge_sh, mask, fc_w1, fc_b1);
    node_kernel<<<NNODE / 2, 256, SMEM_BYTES>>>(node_attr, mask,
                                    w_lin_in_s, w_lin_in_v,
                                    fc_w2, fc_b2, w_lin_out_s, w_lin_out_v, out);
}